// round 5
// baseline (speedup 1.0000x reference)
#include <cuda_runtime.h>

// Problem constants
#define Bn   64
#define Rn   4608
#define Cn   32
#define INn  8
#define OUTn 16
#define RCHUNK 64
#define NCHUNK 72    // Rn / RCHUNK

typedef unsigned long long ull;

// Scratch (device globals; allocation-free per harness rules)
static __device__ float4 g_xT4[(size_t)Rn * 2 * Bn];               // x transposed: [r][h][b] float4
static __device__ float  g_red[(size_t)Cn * NCHUNK * Bn * 17];     // pass partials (n[16], d)
static __device__ float  g_v1[(size_t)Bn * Cn * OUTn];
static __device__ float  g_vcur[(size_t)Bn * Cn * OUTn];           // logit vector (zero-init; iter1 ignores)

// ---- packed f32x2 helpers ----
__device__ __forceinline__ ull pk2(float lo, float hi) {
    ull r;
    asm("mov.b64 %0, {%1, %2};" : "=l"(r) : "f"(lo), "f"(hi));
    return r;
}
__device__ __forceinline__ ull ffma2(ull a, ull b, ull c) {
    ull d;
    asm("fma.rn.f32x2 %0, %1, %2, %3;" : "=l"(d) : "l"(a), "l"(b), "l"(c));
    return d;
}
__device__ __forceinline__ float2 upk2(ull v) {
    float lo, hi;
    asm("mov.b64 {%0, %1}, %2;" : "=f"(lo), "=f"(hi) : "l"(v));
    return make_float2(lo, hi);
}

// ============================================================================
// k0: transpose x (64 b, 9216 float4-cols) -> xT (9216 rows, 64 b).
// ============================================================================
__global__ void __launch_bounds__(256)
k0_transpose(const float4* __restrict__ x4) {
    __shared__ float4 tile[32][33];
    const int f0 = blockIdx.x * 32;
    const int b0 = blockIdx.y * 32;
    const int tx = threadIdx.x;
    const int ty0 = threadIdx.y;
    #pragma unroll
    for (int j = 0; j < 4; j++) {
        int ty = ty0 * 4 + j;
        tile[ty][tx] = x4[(size_t)(b0 + ty) * (Rn * 2) + f0 + tx];
    }
    __syncthreads();
    #pragma unroll
    for (int j = 0; j < 4; j++) {
        int ty = ty0 * 4 + j;
        g_xT4[(size_t)(f0 + ty) * Bn + b0 + tx] = tile[tx][ty];
    }
}

// ============================================================================
// kpass: one routing pass, u recomputed on the fly, OUTPUT-SPLIT across
// lane halves. Grid (Cn, NCHUNK). Block 256:
//   warp w: rg = w>>2 (0..1, 32 routes each), bq = w&3
//   lane:   hh = lane>>4 (which 8 outputs), b = bq*16 + (lane&15)
// Per thread: 8-output accumulators only (~60 regs). Full 16-dim logit dot
// completed by shfl_xor(16) between the two halves.
// mode 0: e = 1 (iteration-1 plain sum). mode 1: e = exp(u . v).
// ============================================================================
__global__ void __launch_bounds__(256)
kpass(int mode, const float* __restrict__ w) {
    const int c     = blockIdx.x;
    const int chunk = blockIdx.y;
    const int r0    = chunk * RCHUNK;
    const int tid   = threadIdx.x;
    const int warp  = tid >> 5;
    const int lane  = tid & 31;
    const int rg    = warp >> 2;            // 0..1 (32 routes each)
    const int bq    = warp & 3;
    const int hh    = lane >> 4;            // output half
    const int b     = bq * 16 + (lane & 15);

    __shared__ float sW[RCHUNK * 128];   // 32 KB: W[r0..r0+63][c][i][o]; reused for reduction
    __shared__ float sV[Bn * OUTn];      // 4 KB

    // Stage W chunk (coalesced float4)
    {
        const float4* wg = reinterpret_cast<const float4*>(w);
        float4*       ws = reinterpret_cast<float4*>(sW);
        #pragma unroll
        for (int t = tid; t < RCHUNK * 32; t += 256) {
            int rr = t >> 5;
            int q  = t & 31;
            ws[rr * 32 + q] = wg[((size_t)(r0 + rr) * Cn + c) * 32 + q];
        }
    }
    for (int t = tid; t < Bn * OUTn; t += 256) {
        int b_ = t >> 4, o_ = t & 15;
        sV[t] = g_vcur[((size_t)b_ * Cn + c) * OUTn + o_];
    }
    __syncthreads();

    float v[8];
    #pragma unroll
    for (int j = 0; j < 8; j++) v[j] = sV[b * OUTn + hh * 8 + j];

    float d = 0.f;
    float n[8];
    #pragma unroll
    for (int j = 0; j < 8; j++) n[j] = 0.f;

    #pragma unroll 4
    for (int k = 0; k < 32; k++) {
        const int rr = rg * 32 + k;
        const int r  = r0 + rr;

        // x row (8 floats); L2-hot, coalesced across the 16-lane half
        float4 xa = g_xT4[((size_t)r * 2 + 0) * Bn + b];
        float4 xb = g_xT4[((size_t)r * 2 + 1) * Bn + b];
        float xv[8] = {xa.x, xa.y, xa.z, xa.w, xb.x, xb.y, xb.z, xb.w};

        // u_half = W_r[:, hh*8 : hh*8+8]^T x   (4 f32x2 accumulators)
        ull acc[4];
        #pragma unroll
        for (int jp = 0; jp < 4; jp++) acc[jp] = 0ull;

        const ulonglong2* wr =
            reinterpret_cast<const ulonglong2*>(sW + rr * 128 + hh * 8);
        #pragma unroll
        for (int i = 0; i < 8; i++) {
            ull x2 = pk2(xv[i], xv[i]);
            ulonglong2 p0 = wr[i * 4 + 0];   // 2 distinct 16B segs per warp: conflict-free
            ulonglong2 p1 = wr[i * 4 + 1];
            acc[0] = ffma2(x2, p0.x, acc[0]);
            acc[1] = ffma2(x2, p0.y, acc[1]);
            acc[2] = ffma2(x2, p1.x, acc[2]);
            acc[3] = ffma2(x2, p1.y, acc[3]);
        }

        float u[8];
        #pragma unroll
        for (int jp = 0; jp < 4; jp++) {
            float2 f = upk2(acc[jp]);
            u[2 * jp]     = f.x;
            u[2 * jp + 1] = f.y;
        }

        float e;
        if (mode) {
            float t = 0.f;
            #pragma unroll
            for (int j = 0; j < 8; j++) t = fmaf(u[j], v[j], t);
            t += __shfl_xor_sync(0xffffffffu, t, 16);   // full 16-dim logit
            e = __expf(t);                               // bounded; no max-sub
        } else {
            e = 1.0f;
        }
        d += e;
        #pragma unroll
        for (int j = 0; j < 8; j++) n[j] = fmaf(e, u[j], n[j]);
    }

    // ---- reduce over the 2 r-groups; write per-(c,chunk,b) partials ----
    __syncthreads();                 // done with sW contents
    float* sred = sW;                // [2 rg][64 b][17]
    float* sr = sred + ((size_t)rg * Bn + b) * 17;
    #pragma unroll
    for (int j = 0; j < 8; j++) sr[hh * 8 + j] = n[j];
    if (hh == 0) sr[16] = d;
    __syncthreads();

    for (int t = tid; t < Bn * 17; t += 256) {
        int b_ = t / 17, o_ = t % 17;
        g_red[(((size_t)c * NCHUNK + chunk) * Bn + b_) * 17 + o_] =
            sred[((0 * Bn + b_)) * 17 + o_] + sred[((1 * Bn + b_)) * 17 + o_];
    }
}

// ============================================================================
// kf_v1: v1 = squash(mean_r u_r) from pass-0 partials; seeds g_vcur = v1.
// ============================================================================
__global__ void __launch_bounds__(32)
kf_v1() {
    const int bc = blockIdx.x;
    const int b  = bc >> 5;
    const int c  = bc & 31;
    const int t  = threadIdx.x;

    float acc = 0.f;
    if (t < OUTn) {
        for (int ch = 0; ch < NCHUNK; ch++)
            acc += g_red[(((size_t)c * NCHUNK + ch) * Bn + b) * 17 + t];
    }
    float val = (t < OUTn) ? acc * (1.0f / Rn) : 0.f;
    float sq = val * val;
    #pragma unroll
    for (int off = 16; off; off >>= 1) sq += __shfl_xor_sync(0xffffffffu, sq, off);
    float coef = (sq / (1.f + sq)) * rsqrtf(sq + 1e-8f);
    float v = val * coef;
    if (t < OUTn) {
        g_v1[(size_t)bc * OUTn + t]   = v;
        g_vcur[(size_t)bc * OUTn + t] = v;
    }
}

// ============================================================================
// kf_fin: reduce chunk partials -> softmax-weighted sum -> squash.
// mode 0: g_vcur = v1 + v2 (logits for pass 3).  mode 1: write v3 to out.
// ============================================================================
__global__ void __launch_bounds__(32)
kf_fin(int mode, float* __restrict__ out) {
    const int bc = blockIdx.x;
    const int b  = bc >> 5;
    const int c  = bc & 31;
    const int t  = threadIdx.x;

    float acc = 0.f;
    if (t < 17) {
        for (int ch = 0; ch < NCHUNK; ch++)
            acc += g_red[(((size_t)c * NCHUNK + ch) * Bn + b) * 17 + t];
    }
    float D = __shfl_sync(0xffffffffu, acc, 16);
    float val = (t < OUTn) ? acc / D : 0.f;
    float sq = val * val;
    #pragma unroll
    for (int off = 16; off; off >>= 1) sq += __shfl_xor_sync(0xffffffffu, sq, off);
    float coef = (sq / (1.f + sq)) * rsqrtf(sq + 1e-8f);
    float v = val * coef;
    if (t < OUTn) {
        if (mode == 0)
            g_vcur[(size_t)bc * OUTn + t] = g_v1[(size_t)bc * OUTn + t] + v;
        else
            out[(size_t)bc * OUTn + t] = v;
    }
}

// ============================================================================
extern "C" void kernel_launch(void* const* d_in, const int* in_sizes, int n_in,
                              void* d_out, int out_size) {
    const float* x = (const float*)d_in[0];           // (64, 4608, 8)
    const float* w = (const float*)d_in[1];           // (4608, 32, 8, 16)
    float* out = (float*)d_out;                       // (64, 32, 16)

    dim3 gp(Cn, NCHUNK);
    k0_transpose<<<dim3(Rn * 2 / 32, Bn / 32), dim3(32, 8)>>>((const float4*)x);
    kpass<<<gp, 256>>>(0, w);          // iteration 1 (e = 1)
    kf_v1<<<Bn * Cn, 32>>>();
    kpass<<<gp, 256>>>(1, w);          // iteration 2
    kf_fin<<<Bn * Cn, 32>>>(0, out);
    kpass<<<gp, 256>>>(1, w);          // iteration 3
    kf_fin<<<Bn * Cn, 32>>>(1, out);
}

// round 6
// speedup vs baseline: 1.4979x; 1.4979x over previous
#include <cuda_runtime.h>
#include <cuda_fp16.h>

// Problem constants
#define Bn   64
#define Rn   4608
#define Cn   32
#define INn  8
#define OUTn 16
#define RCHUNK 64
#define NCHUNK 72    // Rn / RCHUNK
#define RPASS  128
#define NSPLIT 36    // Rn / RPASS

typedef unsigned long long ull;

// Scratch (device globals; allocation-free per harness rules)
// u_hat layout: [c][r][h(2)][b(64)] of uint4 (8 fp16 each) -> dense 512B warp accesses
static __device__ uint4  g_uhat4[(size_t)Cn * Rn * 2 * Bn];          // 302 MB
static __device__ float4 g_xT4[(size_t)Rn * 2 * Bn];                 // x transposed: [r][h][b] float4
static __device__ float  g_part[(size_t)Cn * NCHUNK * Bn * OUTn];    // iter-1 partial sums (exact fp32)
static __device__ float  g_red[(size_t)Cn * NSPLIT * Bn * 17];       // pass partials (n[16], d)
static __device__ float  g_v1[(size_t)Bn * Cn * OUTn];
static __device__ float  g_vcur[(size_t)Bn * Cn * OUTn];             // current logit vector

// ---- packed f32x2 helpers ----
__device__ __forceinline__ ull pk2(float lo, float hi) {
    ull r;
    asm("mov.b64 %0, {%1, %2};" : "=l"(r) : "f"(lo), "f"(hi));
    return r;
}
__device__ __forceinline__ ull ffma2(ull a, ull b, ull c) {
    ull d;
    asm("fma.rn.f32x2 %0, %1, %2, %3;" : "=l"(d) : "l"(a), "l"(b), "l"(c));
    return d;
}
__device__ __forceinline__ float2 upk2(ull v) {
    float lo, hi;
    asm("mov.b64 {%0, %1}, %2;" : "=f"(lo), "=f"(hi) : "l"(v));
    return make_float2(lo, hi);
}

// ============================================================================
// k0: transpose x (64 b, 9216 float4-cols) -> xT (9216 rows, 64 b).
// ============================================================================
__global__ void __launch_bounds__(256)
k0_transpose(const float4* __restrict__ x4) {
    __shared__ float4 tile[32][33];
    const int f0 = blockIdx.x * 32;
    const int b0 = blockIdx.y * 32;
    const int tx = threadIdx.x;
    const int ty0 = threadIdx.y;
    #pragma unroll
    for (int j = 0; j < 4; j++) {
        int ty = ty0 * 4 + j;
        tile[ty][tx] = x4[(size_t)(b0 + ty) * (Rn * 2) + f0 + tx];
    }
    __syncthreads();
    #pragma unroll
    for (int j = 0; j < 4; j++) {
        int ty = ty0 * 4 + j;
        g_xT4[(size_t)(f0 + ty) * Bn + b0 + tx] = tile[tx][ty];
    }
}

// ============================================================================
// k1 (R2's measured-good version): u_hat fp16 (dense layout) + exact fp32
// iter-1 partial sums. Grid (Cn, NCHUNK), block 256 = 4 rgroups x 64 b.
// Warp lanes = consecutive b with identical r -> W smem reads broadcast,
// x loads and u_hat stores fully coalesced.
// ============================================================================
__global__ void __launch_bounds__(256)
k1_uhat(const float* __restrict__ w) {
    const int c     = blockIdx.x;
    const int chunk = blockIdx.y;
    const int r0    = chunk * RCHUNK;
    const int tid   = threadIdx.x;

    __shared__ float sW[RCHUNK * 128];   // 32 KB: W[r0..r0+63][c][i][o]

    {
        const float4* wg = reinterpret_cast<const float4*>(w);
        float4*       ws = reinterpret_cast<float4*>(sW);
        #pragma unroll
        for (int t = tid; t < RCHUNK * 32; t += 256) {
            int rr = t >> 5;
            int q  = t & 31;
            ws[rr * 32 + q] = wg[((size_t)(r0 + rr) * Cn + c) * 32 + q];
        }
    }
    __syncthreads();

    const int rgroup = tid >> 6;       // 0..3
    const int bb     = tid & 63;       // batch (lane-contiguous)

    float sacc[OUTn];
    #pragma unroll
    for (int o = 0; o < OUTn; o++) sacc[o] = 0.f;

    for (int k = 0; k < RCHUNK / 4; k++) {
        const int rr = rgroup * (RCHUNK / 4) + k;
        const int r  = r0 + rr;

        // x row (8 floats) — dense: lanes read consecutive float4
        float4 xa = g_xT4[((size_t)r * 2 + 0) * Bn + bb];
        float4 xb = g_xT4[((size_t)r * 2 + 1) * Bn + bb];
        float xv[8] = {xa.x, xa.y, xa.z, xa.w, xb.x, xb.y, xb.z, xb.w};

        ull acc[8];
        #pragma unroll
        for (int j = 0; j < 8; j++) acc[j] = 0ull;

        const ull* wr = reinterpret_cast<const ull*>(sW + rr * 128);
        #pragma unroll
        for (int i = 0; i < 8; i++) {
            ull x2 = pk2(xv[i], xv[i]);
            #pragma unroll
            for (int j = 0; j < 8; j++) {
                acc[j] = ffma2(x2, wr[i * 8 + j], acc[j]);   // broadcast LDS.64
            }
        }

        union { __half2 h[8]; uint4 q[2]; } cv;
        #pragma unroll
        for (int j = 0; j < 8; j++) {
            float2 u = upk2(acc[j]);
            sacc[2 * j]     += u.x;
            sacc[2 * j + 1] += u.y;
            cv.h[j] = __floats2half2_rn(u.x, u.y);
        }
        // dense stores: [c][r][h][b]
        size_t base = ((size_t)(c * Rn + r) * 2) * Bn + bb;
        g_uhat4[base]      = cv.q[0];
        g_uhat4[base + Bn] = cv.q[1];
    }

    // Reduce sacc across the 4 r-groups per batch (fixed order)
    __syncthreads();
    float* sred = sW;
    #pragma unroll
    for (int o = 0; o < OUTn; o++) sred[tid * OUTn + o] = sacc[o];
    __syncthreads();
    if (tid < 64) {
        #pragma unroll
        for (int o = 0; o < OUTn; o++) {
            float s = sred[tid * OUTn + o]
                    + sred[(64  + tid) * OUTn + o]
                    + sred[(128 + tid) * OUTn + o]
                    + sred[(192 + tid) * OUTn + o];
            g_part[(((size_t)c * NCHUNK + chunk) * Bn + tid) * OUTn + o] = s;
        }
    }
}

// ============================================================================
// kf_v1: v1 = squash(mean_r u_r) per (b,c); seeds g_vcur = v1.
// ============================================================================
__global__ void __launch_bounds__(32)
kf_v1() {
    const int bc = blockIdx.x;
    const int b  = bc >> 5;
    const int c  = bc & 31;
    const int t  = threadIdx.x;

    float acc = 0.f;
    if (t < OUTn) {
        for (int ch = 0; ch < NCHUNK; ch++)
            acc += g_part[(((size_t)c * NCHUNK + ch) * Bn + b) * OUTn + t];
    }
    float val = (t < OUTn) ? acc * (1.0f / Rn) : 0.f;
    float sq = val * val;
    #pragma unroll
    for (int off = 16; off; off >>= 1) sq += __shfl_xor_sync(0xffffffffu, sq, off);
    float coef = (sq / (1.f + sq)) * rsqrtf(sq + 1e-8f);
    float v = val * coef;
    if (t < OUTn) {
        g_v1[(size_t)bc * OUTn + t]   = v;
        g_vcur[(size_t)bc * OUTn + t] = v;
    }
}

// ============================================================================
// k2p (R3's measured-good version, 54.4us): streaming routing pass,
// o-split across lane pairs. CTA = (c, 128-r slab).
// Warp = (rgroup 0..1, bquad 0..3); lane = 16 b x 2 h.
// ============================================================================
__global__ void __launch_bounds__(256)
k2p() {
    const int c     = blockIdx.x;
    const int split = blockIdx.y;
    const int tid   = threadIdx.x;
    const int warp  = tid >> 5;
    const int lane  = tid & 31;
    const int rg    = warp >> 2;            // 0..1 (64 r each)
    const int bq    = warp & 3;             // 0..3
    const int hh    = lane >> 4;            // 0/1 (which 8 outputs)
    const int b     = bq * 16 + (lane & 15);

    __shared__ float sV[Bn * OUTn];
    __shared__ float sRed[2][Bn][18];

    for (int t = tid; t < Bn * OUTn; t += 256) {
        int b_ = t >> 4, o_ = t & 15;
        sV[t] = g_vcur[((size_t)b_ * Cn + c) * OUTn + o_];
    }
    __syncthreads();

    float v[8];
    #pragma unroll
    for (int j = 0; j < 8; j++) v[j] = sV[b * OUTn + hh * 8 + j];

    float d = 0.f;
    float n[8];
    #pragma unroll
    for (int j = 0; j < 8; j++) n[j] = 0.f;

    const int rbase = split * RPASS + rg * 64;
    size_t base = ((size_t)(c * Rn + rbase) * 2 + hh) * Bn + b;

    #pragma unroll 4
    for (int k = 0; k < 64; k++) {
        uint4 q = g_uhat4[base + (size_t)k * 2 * Bn];
        union { __half2 h[4]; uint4 q4; } cv;
        cv.q4 = q;
        float u[8];
        #pragma unroll
        for (int j = 0; j < 4; j++) {
            float2 f = __half22float2(cv.h[j]);
            u[2 * j]     = f.x;
            u[2 * j + 1] = f.y;
        }
        float t = 0.f;
        #pragma unroll
        for (int j = 0; j < 8; j++) t = fmaf(u[j], v[j], t);
        t += __shfl_xor_sync(0xffffffffu, t, 16);       // full 16-dim dot
        float e = __expf(t);
        d += e;
        #pragma unroll
        for (int j = 0; j < 8; j++) n[j] = fmaf(e, u[j], n[j]);
    }

    #pragma unroll
    for (int j = 0; j < 8; j++) sRed[rg][b][hh * 8 + j] = n[j];
    if (hh == 0) sRed[rg][b][16] = d;
    __syncthreads();

    for (int t = tid; t < Bn * 17; t += 256) {
        int b_ = t / 17, o_ = t % 17;
        g_red[(((size_t)c * NSPLIT + split) * Bn + b_) * 17 + o_] =
            sRed[0][b_][o_] + sRed[1][b_][o_];
    }
}

// ============================================================================
// kf_fin: reduce slab partials -> softmax-weighted sum -> squash.
// mode 0: g_vcur = v1 + v2.  mode 1: write v3 to out.
// ============================================================================
__global__ void __launch_bounds__(32)
kf_fin(int mode, float* __restrict__ out) {
    const int bc = blockIdx.x;
    const int b  = bc >> 5;
    const int c  = bc & 31;
    const int t  = threadIdx.x;

    float acc = 0.f;
    if (t < 17) {
        for (int s = 0; s < NSPLIT; s++)
            acc += g_red[(((size_t)c * NSPLIT + s) * Bn + b) * 17 + t];
    }
    float D = __shfl_sync(0xffffffffu, acc, 16);
    float val = (t < OUTn) ? acc / D : 0.f;
    float sq = val * val;
    #pragma unroll
    for (int off = 16; off; off >>= 1) sq += __shfl_xor_sync(0xffffffffu, sq, off);
    float coef = (sq / (1.f + sq)) * rsqrtf(sq + 1e-8f);
    float v = val * coef;
    if (t < OUTn) {
        if (mode == 0)
            g_vcur[(size_t)bc * OUTn + t] = g_v1[(size_t)bc * OUTn + t] + v;
        else
            out[(size_t)bc * OUTn + t] = v;
    }
}

// ============================================================================
extern "C" void kernel_launch(void* const* d_in, const int* in_sizes, int n_in,
                              void* d_out, int out_size) {
    const float* x = (const float*)d_in[0];           // (64, 4608, 8)
    const float* w = (const float*)d_in[1];           // (4608, 32, 8, 16)
    float* out = (float*)d_out;                       // (64, 32, 16)

    k0_transpose<<<dim3(Rn * 2 / 32, Bn / 32), dim3(32, 8)>>>((const float4*)x);
    k1_uhat<<<dim3(Cn, NCHUNK), 256>>>(w);
    kf_v1<<<Bn * Cn, 32>>>();
    k2p<<<dim3(Cn, NSPLIT), 256>>>();
    kf_fin<<<Bn * Cn, 32>>>(0, out);
    k2p<<<dim3(Cn, NSPLIT), 256>>>();
    kf_fin<<<Bn * Cn, 32>>>(1, out);
}

// round 7
// speedup vs baseline: 1.5679x; 1.0467x over previous
#include <cuda_runtime.h>
#include <cuda_fp16.h>

// Problem constants
#define Bn   64
#define Rn   4608
#define Cn   32
#define INn  8
#define OUTn 16
#define RCHUNK 64
#define NCHUNK 72    // Rn / RCHUNK
#define RPASS  128
#define NSPLIT 36    // Rn / RPASS

typedef unsigned long long ull;

// Scratch (device globals; allocation-free per harness rules)
// u_hat layout: [c][r][h(2)][b(64)] of uint4 (8 fp16 each) -> dense 512B warp accesses
static __device__ uint4  g_uhat4[(size_t)Cn * Rn * 2 * Bn];          // 302 MB
static __device__ float4 g_xT4[(size_t)Rn * 2 * Bn];                 // x transposed: [r][h][b] float4
static __device__ float  g_part[(size_t)Cn * NCHUNK * Bn * OUTn];    // iter-1 partial sums (exact fp32)
static __device__ float  g_red[(size_t)Cn * NSPLIT * Bn * 17];       // pass partials (n[16], d)
static __device__ float  g_v1[(size_t)Bn * Cn * OUTn];
static __device__ float  g_vcur[(size_t)Bn * Cn * OUTn];             // current logit vector

// ---- packed f32x2 helpers ----
__device__ __forceinline__ ull pk2(float lo, float hi) {
    ull r;
    asm("mov.b64 %0, {%1, %2};" : "=l"(r) : "f"(lo), "f"(hi));
    return r;
}
__device__ __forceinline__ ull ffma2(ull a, ull b, ull c) {
    ull d;
    asm("fma.rn.f32x2 %0, %1, %2, %3;" : "=l"(d) : "l"(a), "l"(b), "l"(c));
    return d;
}
__device__ __forceinline__ ull fadd2(ull a, ull b) {
    ull d;
    asm("add.rn.f32x2 %0, %1, %2;" : "=l"(d) : "l"(a), "l"(b));
    return d;
}
__device__ __forceinline__ float2 upk2(ull v) {
    float lo, hi;
    asm("mov.b64 {%0, %1}, %2;" : "=f"(lo), "=f"(hi) : "l"(v));
    return make_float2(lo, hi);
}

// ============================================================================
// k0: transpose x (64 b, 9216 float4-cols) -> xT (9216 rows, 64 b).
// ============================================================================
__global__ void __launch_bounds__(256)
k0_transpose(const float4* __restrict__ x4) {
    __shared__ float4 tile[32][33];
    const int f0 = blockIdx.x * 32;
    const int b0 = blockIdx.y * 32;
    const int tx = threadIdx.x;
    const int ty0 = threadIdx.y;
    #pragma unroll
    for (int j = 0; j < 4; j++) {
        int ty = ty0 * 4 + j;
        tile[ty][tx] = x4[(size_t)(b0 + ty) * (Rn * 2) + f0 + tx];
    }
    __syncthreads();
    #pragma unroll
    for (int j = 0; j < 4; j++) {
        int ty = ty0 * 4 + j;
        g_xT4[(size_t)(f0 + ty) * Bn + b0 + tx] = tile[tx][ty];
    }
}

// ============================================================================
// k1: u_hat fp16 (dense layout) + exact fp32 iter-1 partials.
// 2-BATCH BLOCKED: block 256 = 8 warps; warp = one 8-route group,
// lane = b-pair (b = lane, lane+32). Each smem W value feeds 2 FFMA2
// (LDS stream halved vs R6). Accumulators packed f32x2 to cap registers.
// ============================================================================
__global__ void __launch_bounds__(256)
k1_uhat(const float* __restrict__ w) {
    const int c     = blockIdx.x;
    const int chunk = blockIdx.y;
    const int r0    = chunk * RCHUNK;
    const int tid   = threadIdx.x;
    const int warp  = tid >> 5;        // rgroup 0..7 (8 routes each)
    const int lane  = tid & 31;        // b0 = lane, b1 = lane + 32

    __shared__ float sW[RCHUNK * 128];   // 32 KB: W[r0..r0+63][c][i][o]; reused for reduction

    {
        const float4* wg = reinterpret_cast<const float4*>(w);
        float4*       ws = reinterpret_cast<float4*>(sW);
        #pragma unroll
        for (int t = tid; t < RCHUNK * 32; t += 256) {
            int rr = t >> 5;
            int q  = t & 31;
            ws[rr * 32 + q] = wg[((size_t)(r0 + rr) * Cn + c) * 32 + q];
        }
    }
    __syncthreads();

    ull sacc0[8], sacc1[8];            // packed f32x2 iter-1 accumulators
    #pragma unroll
    for (int j = 0; j < 8; j++) { sacc0[j] = 0ull; sacc1[j] = 0ull; }

    for (int k = 0; k < 8; k++) {
        const int rr = warp * 8 + k;
        const int r  = r0 + rr;

        // x rows for both batches (dense across lanes, L2-hot)
        float4 xa0 = g_xT4[((size_t)r * 2 + 0) * Bn + lane];
        float4 xb0 = g_xT4[((size_t)r * 2 + 1) * Bn + lane];
        float4 xa1 = g_xT4[((size_t)r * 2 + 0) * Bn + lane + 32];
        float4 xb1 = g_xT4[((size_t)r * 2 + 1) * Bn + lane + 32];
        float xv0[8] = {xa0.x, xa0.y, xa0.z, xa0.w, xb0.x, xb0.y, xb0.z, xb0.w};
        float xv1[8] = {xa1.x, xa1.y, xa1.z, xa1.w, xb1.x, xb1.y, xb1.z, xb1.w};

        ull acc0[8], acc1[8];
        #pragma unroll
        for (int j = 0; j < 8; j++) { acc0[j] = 0ull; acc1[j] = 0ull; }

        const ull* wr = reinterpret_cast<const ull*>(sW + rr * 128);
        #pragma unroll
        for (int i = 0; i < 8; i++) {
            ull x20 = pk2(xv0[i], xv0[i]);
            ull x21 = pk2(xv1[i], xv1[i]);
            #pragma unroll
            for (int j = 0; j < 8; j++) {
                ull wv = wr[i * 8 + j];            // broadcast LDS.64, reused 2x
                acc0[j] = ffma2(x20, wv, acc0[j]);
                acc1[j] = ffma2(x21, wv, acc1[j]);
            }
        }

        union { __half2 h[8]; uint4 q[2]; } cv0, cv1;
        #pragma unroll
        for (int j = 0; j < 8; j++) {
            sacc0[j] = fadd2(sacc0[j], acc0[j]);
            sacc1[j] = fadd2(sacc1[j], acc1[j]);
            float2 u0 = upk2(acc0[j]);
            float2 u1 = upk2(acc1[j]);
            cv0.h[j] = __floats2half2_rn(u0.x, u0.y);
            cv1.h[j] = __floats2half2_rn(u1.x, u1.y);
        }
        // dense stores: [c][r][h][b]
        size_t base = ((size_t)(c * Rn + r) * 2) * Bn + lane;
        g_uhat4[base]           = cv0.q[0];
        g_uhat4[base + Bn]      = cv0.q[1];
        g_uhat4[base + 32]      = cv1.q[0];
        g_uhat4[base + Bn + 32] = cv1.q[1];
    }

    // ---- reduce iter-1 partials over the 8 rgroups (fixed order) ----
    __syncthreads();                    // done with sW contents
    float* sred = sW;                   // [8 rg][64 b][16 o] = 32 KB
    #pragma unroll
    for (int j = 0; j < 8; j++) {
        float2 u0 = upk2(sacc0[j]);
        float2 u1 = upk2(sacc1[j]);
        sred[((size_t)warp * Bn + lane) * OUTn + 2 * j]          = u0.x;
        sred[((size_t)warp * Bn + lane) * OUTn + 2 * j + 1]      = u0.y;
        sred[((size_t)warp * Bn + lane + 32) * OUTn + 2 * j]     = u1.x;
        sred[((size_t)warp * Bn + lane + 32) * OUTn + 2 * j + 1] = u1.y;
    }
    __syncthreads();
    #pragma unroll
    for (int s = 0; s < 4; s++) {
        int idx = tid * 4 + s;
        int b_ = idx >> 4, o_ = idx & 15;
        float acc = 0.f;
        #pragma unroll
        for (int rg = 0; rg < 8; rg++)
            acc += sred[((size_t)rg * Bn + b_) * OUTn + o_];
        g_part[(((size_t)c * NCHUNK + chunk) * Bn + b_) * OUTn + o_] = acc;
    }
}

// ============================================================================
// kf_v1: v1 = squash(mean_r u_r) per (b,c); seeds g_vcur = v1.
// ============================================================================
__global__ void __launch_bounds__(32)
kf_v1() {
    const int bc = blockIdx.x;
    const int b  = bc >> 5;
    const int c  = bc & 31;
    const int t  = threadIdx.x;

    float acc = 0.f;
    if (t < OUTn) {
        for (int ch = 0; ch < NCHUNK; ch++)
            acc += g_part[(((size_t)c * NCHUNK + ch) * Bn + b) * OUTn + t];
    }
    float val = (t < OUTn) ? acc * (1.0f / Rn) : 0.f;
    float sq = val * val;
    #pragma unroll
    for (int off = 16; off; off >>= 1) sq += __shfl_xor_sync(0xffffffffu, sq, off);
    float coef = (sq / (1.f + sq)) * rsqrtf(sq + 1e-8f);
    float v = val * coef;
    if (t < OUTn) {
        g_v1[(size_t)bc * OUTn + t]   = v;
        g_vcur[(size_t)bc * OUTn + t] = v;
    }
}

// ============================================================================
// k2p: streaming routing pass, o-split across lane pairs (measured 54-56us).
// unroll bumped 4 -> 8 for more loads in flight.
// ============================================================================
__global__ void __launch_bounds__(256)
k2p() {
    const int c     = blockIdx.x;
    const int split = blockIdx.y;
    const int tid   = threadIdx.x;
    const int warp  = tid >> 5;
    const int lane  = tid & 31;
    const int rg    = warp >> 2;            // 0..1 (64 r each)
    const int bq    = warp & 3;             // 0..3
    const int hh    = lane >> 4;            // 0/1 (which 8 outputs)
    const int b     = bq * 16 + (lane & 15);

    __shared__ float sV[Bn * OUTn];
    __shared__ float sRed[2][Bn][18];

    for (int t = tid; t < Bn * OUTn; t += 256) {
        int b_ = t >> 4, o_ = t & 15;
        sV[t] = g_vcur[((size_t)b_ * Cn + c) * OUTn + o_];
    }
    __syncthreads();

    float v[8];
    #pragma unroll
    for (int j = 0; j < 8; j++) v[j] = sV[b * OUTn + hh * 8 + j];

    float d = 0.f;
    float n[8];
    #pragma unroll
    for (int j = 0; j < 8; j++) n[j] = 0.f;

    const int rbase = split * RPASS + rg * 64;
    size_t base = ((size_t)(c * Rn + rbase) * 2 + hh) * Bn + b;

    #pragma unroll 8
    for (int k = 0; k < 64; k++) {
        uint4 q = g_uhat4[base + (size_t)k * 2 * Bn];
        union { __half2 h[4]; uint4 q4; } cv;
        cv.q4 = q;
        float u[8];
        #pragma unroll
        for (int j = 0; j < 4; j++) {
            float2 f = __half22float2(cv.h[j]);
            u[2 * j]     = f.x;
            u[2 * j + 1] = f.y;
        }
        float t = 0.f;
        #pragma unroll
        for (int j = 0; j < 8; j++) t = fmaf(u[j], v[j], t);
        t += __shfl_xor_sync(0xffffffffu, t, 16);       // full 16-dim dot
        float e = __expf(t);
        d += e;
        #pragma unroll
        for (int j = 0; j < 8; j++) n[j] = fmaf(e, u[j], n[j]);
    }

    #pragma unroll
    for (int j = 0; j < 8; j++) sRed[rg][b][hh * 8 + j] = n[j];
    if (hh == 0) sRed[rg][b][16] = d;
    __syncthreads();

    for (int t = tid; t < Bn * 17; t += 256) {
        int b_ = t / 17, o_ = t % 17;
        g_red[(((size_t)c * NSPLIT + split) * Bn + b_) * 17 + o_] =
            sRed[0][b_][o_] + sRed[1][b_][o_];
    }
}

// ============================================================================
// kf_fin: reduce slab partials -> softmax-weighted sum -> squash.
// mode 0: g_vcur = v1 + v2.  mode 1: write v3 to out.
// ============================================================================
__global__ void __launch_bounds__(32)
kf_fin(int mode, float* __restrict__ out) {
    const int bc = blockIdx.x;
    const int b  = bc >> 5;
    const int c  = bc & 31;
    const int t  = threadIdx.x;

    float acc = 0.f;
    if (t < 17) {
        for (int s = 0; s < NSPLIT; s++)
            acc += g_red[(((size_t)c * NSPLIT + s) * Bn + b) * 17 + t];
    }
    float D = __shfl_sync(0xffffffffu, acc, 16);
    float val = (t < OUTn) ? acc / D : 0.f;
    float sq = val * val;
    #pragma unroll
    for (int off = 16; off; off >>= 1) sq += __shfl_xor_sync(0xffffffffu, sq, off);
    float coef = (sq / (1.f + sq)) * rsqrtf(sq + 1e-8f);
    float v = val * coef;
    if (t < OUTn) {
        if (mode == 0)
            g_vcur[(size_t)bc * OUTn + t] = g_v1[(size_t)bc * OUTn + t] + v;
        else
            out[(size_t)bc * OUTn + t] = v;
    }
}

// ============================================================================
extern "C" void kernel_launch(void* const* d_in, const int* in_sizes, int n_in,
                              void* d_out, int out_size) {
    const float* x = (const float*)d_in[0];           // (64, 4608, 8)
    const float* w = (const float*)d_in[1];           // (4608, 32, 8, 16)
    float* out = (float*)d_out;                       // (64, 32, 16)

    k0_transpose<<<dim3(Rn * 2 / 32, Bn / 32), dim3(32, 8)>>>((const float4*)x);
    k1_uhat<<<dim3(Cn, NCHUNK), 256>>>(w);
    kf_v1<<<Bn * Cn, 32>>>();
    k2p<<<dim3(Cn, NSPLIT), 256>>>();
    kf_fin<<<Bn * Cn, 32>>>(0, out);
    k2p<<<dim3(Cn, NSPLIT), 256>>>();
    kf_fin<<<Bn * Cn, 32>>>(1, out);
}